// round 2
// baseline (speedup 1.0000x reference)
#include <cuda_runtime.h>

#define LOG2E 1.44269504088896f

// Scratch: q,k,v in [B*H, S, 64] layout; attn out in [B, S, 1024] layout.
__device__ float g_q[8388608];
__device__ float g_k[8388608];
__device__ float g_v[8388608];
__device__ float g_attn[8388608];

// ---------------------------------------------------------------------------
// Fused QKV projection (+RoPE for Q,K).  C = X @ W^T, W in {Wq,Wk,Wv}.
// BM=128, BN=64, BK=32, 256 threads, 8x4 per thread.
// Smem stored k-major (transposed) so inner loop is 3x LDS.128 + 32 FFMA.
// ---------------------------------------------------------------------------
__global__ __launch_bounds__(256) void qkv_proj_kernel(
    const float* __restrict__ X,
    const float* __restrict__ Wq, const float* __restrict__ Wk,
    const float* __restrict__ Wv,
    const float* __restrict__ cos_f, const float* __restrict__ sin_f)
{
    __shared__ float As[32 * 132];   // [k][m], pitch 132 (16B-aligned float4 reads)
    __shared__ float Bs[32 * 68];    // [k][n], pitch 68

    const int tid = threadIdx.x;
    const int tx = tid & 15, ty = tid >> 4;
    const int bx = blockIdx.x;              // 0..47
    const int wsel = bx >> 4;               // 0=q, 1=k, 2=v
    const int nt = bx & 15;                 // col tile within matrix (== head)
    const int m0 = blockIdx.y * 128;
    const int n0 = nt * 64;
    const float* __restrict__ W = (wsel == 0) ? Wq : (wsel == 1 ? Wk : Wv);

    float acc[8][4];
    #pragma unroll
    for (int i = 0; i < 8; i++)
        #pragma unroll
        for (int j = 0; j < 4; j++) acc[i][j] = 0.f;

    for (int k0 = 0; k0 < 1024; k0 += 32) {
        #pragma unroll
        for (int i = 0; i < 4; i++) {           // A: 128x32 = 1024 float4
            int idx = tid + i * 256;
            int row = idx >> 3, c4 = idx & 7;
            float4 v = *(const float4*)(X + (size_t)(m0 + row) * 1024 + k0 + c4 * 4);
            int o = (c4 * 4) * 132 + row;
            As[o] = v.x; As[o + 132] = v.y; As[o + 264] = v.z; As[o + 396] = v.w;
        }
        #pragma unroll
        for (int i = 0; i < 2; i++) {           // B: 64x32 = 512 float4
            int idx = tid + i * 256;
            int row = idx >> 3, c4 = idx & 7;
            float4 v = *(const float4*)(W + (size_t)(n0 + row) * 1024 + k0 + c4 * 4);
            int o = (c4 * 4) * 68 + row;
            Bs[o] = v.x; Bs[o + 68] = v.y; Bs[o + 136] = v.z; Bs[o + 204] = v.w;
        }
        __syncthreads();
        #pragma unroll 16
        for (int k = 0; k < 32; k++) {
            float4 b4 = *(const float4*)&Bs[k * 68 + tx * 4];
            float4 a0 = *(const float4*)&As[k * 132 + ty * 8];
            float4 a1 = *(const float4*)&As[k * 132 + ty * 8 + 4];
            float a[8] = {a0.x, a0.y, a0.z, a0.w, a1.x, a1.y, a1.z, a1.w};
            float b[4] = {b4.x, b4.y, b4.z, b4.w};
            #pragma unroll
            for (int ii = 0; ii < 8; ii++)
                #pragma unroll
                for (int jj = 0; jj < 4; jj++)
                    acc[ii][jj] = fmaf(a[ii], b[jj], acc[ii][jj]);
        }
        __syncthreads();
    }

    float* dst = (wsel == 0) ? g_q : (wsel == 1 ? g_k : g_v);
    const int b = m0 >> 11;     // batch (block never straddles: 2048 % 128 == 0)
    const int h = nt;           // 64-wide col tile == one head
    #pragma unroll
    for (int ii = 0; ii < 8; ii++) {
        int m = m0 + ty * 8 + ii;
        int s = m & 2047;
        float4 r;
        if (wsel < 2) {
            // RoPE: cols tx*4..tx*4+3 -> pairs (2i,2i+1) with i = tx*2, tx*2+1
            float c0 = cos_f[s * 32 + tx * 2],     s0 = sin_f[s * 32 + tx * 2];
            float c1 = cos_f[s * 32 + tx * 2 + 1], s1 = sin_f[s * 32 + tx * 2 + 1];
            r.x = acc[ii][0] * c0 - acc[ii][1] * s0;
            r.y = acc[ii][0] * s0 + acc[ii][1] * c0;
            r.z = acc[ii][2] * c1 - acc[ii][3] * s1;
            r.w = acc[ii][2] * s1 + acc[ii][3] * c1;
        } else {
            r = make_float4(acc[ii][0], acc[ii][1], acc[ii][2], acc[ii][3]);
        }
        *(float4*)(dst + ((size_t)(b * 16 + h) * 2048 + s) * 64 + tx * 4) = r;
    }
}

// ---------------------------------------------------------------------------
// Flash attention: 64 q rows x 64 kv per tile, 256 threads, 4x4 per thread
// (strided-free: rows ty*4+ii, cols tx*4+jj).  Online softmax, causal.
// Smem: Qs/Ks d-major [d][row] so score loop is 2x LDS.128 + 16 FFMA per d.
// P reuses the K buffer as [kv][q] so the PV loop is also vector-fed.
// ---------------------------------------------------------------------------
__global__ __launch_bounds__(256) void attn_kernel()
{
    extern __shared__ float sm[];
    float* Qs = sm;               // [64][68]  Qs[d*68 + q]
    float* Ks = sm + 4352;        // [64][68]  Ks[d*68 + kv]; reused as Ps[kv*68 + q]
    float* Vs = sm + 8704;        // [64][68]  Vs[kv*68 + d]

    const int tid = threadIdx.x, tx = tid & 15, ty = tid >> 4;
    const int qt = blockIdx.x, bh = blockIdx.y;
    const int q0 = qt * 64;
    const float* __restrict__ Qg = g_q + (size_t)bh * 2048 * 64;
    const float* __restrict__ Kg = g_k + (size_t)bh * 2048 * 64;
    const float* __restrict__ Vg = g_v + (size_t)bh * 2048 * 64;

    // load Q tile transposed (once)
    #pragma unroll
    for (int i = 0; i < 4; i++) {
        int idx = tid + i * 256;
        int row = idx >> 4, c4 = idx & 15;
        float4 v = *(const float4*)(Qg + (q0 + row) * 64 + c4 * 4);
        int o = (c4 * 4) * 68 + row;
        Qs[o] = v.x; Qs[o + 68] = v.y; Qs[o + 136] = v.z; Qs[o + 204] = v.w;
    }

    float m_i[4], l_i[4], o_acc[4][4];
    #pragma unroll
    for (int i = 0; i < 4; i++) {
        m_i[i] = -1e30f; l_i[i] = 0.f;
        #pragma unroll
        for (int j = 0; j < 4; j++) o_acc[i][j] = 0.f;
    }

    for (int t = 0; t <= qt; t++) {
        const int kv0 = t * 64;
        __syncthreads();   // protects Ps/Vs of previous iter (and Q stores on iter 0)
        #pragma unroll
        for (int i = 0; i < 4; i++) {
            int idx = tid + i * 256;
            int row = idx >> 4, c4 = idx & 15;
            float4 kv = *(const float4*)(Kg + (kv0 + row) * 64 + c4 * 4);
            int o = (c4 * 4) * 68 + row;
            Ks[o] = kv.x; Ks[o + 68] = kv.y; Ks[o + 136] = kv.z; Ks[o + 204] = kv.w;
            float4 vv = *(const float4*)(Vg + (kv0 + row) * 64 + c4 * 4);
            *(float4*)&Vs[row * 68 + c4 * 4] = vv;
        }
        __syncthreads();

        // S = Q @ K^T
        float sacc[4][4];
        #pragma unroll
        for (int i = 0; i < 4; i++)
            #pragma unroll
            for (int j = 0; j < 4; j++) sacc[i][j] = 0.f;
        #pragma unroll 16
        for (int d = 0; d < 64; d++) {
            float4 q4 = *(const float4*)&Qs[d * 68 + ty * 4];
            float4 k4 = *(const float4*)&Ks[d * 68 + tx * 4];
            float qa[4] = {q4.x, q4.y, q4.z, q4.w};
            float ka[4] = {k4.x, k4.y, k4.z, k4.w};
            #pragma unroll
            for (int ii = 0; ii < 4; ii++)
                #pragma unroll
                for (int jj = 0; jj < 4; jj++)
                    sacc[ii][jj] = fmaf(qa[ii], ka[jj], sacc[ii][jj]);
        }

        // scale + causal mask + online softmax
        #pragma unroll
        for (int ii = 0; ii < 4; ii++) {
            const int qi = q0 + ty * 4 + ii;
            float rm = -1e30f;
            #pragma unroll
            for (int jj = 0; jj < 4; jj++) {
                float v = sacc[ii][jj] * 0.125f;
                if (kv0 + tx * 4 + jj > qi) v = -1e9f;
                sacc[ii][jj] = v;
                rm = fmaxf(rm, v);
            }
            rm = fmaxf(rm, __shfl_xor_sync(0xffffffffu, rm, 1));
            rm = fmaxf(rm, __shfl_xor_sync(0xffffffffu, rm, 2));
            rm = fmaxf(rm, __shfl_xor_sync(0xffffffffu, rm, 4));
            rm = fmaxf(rm, __shfl_xor_sync(0xffffffffu, rm, 8));
            float mn = fmaxf(m_i[ii], rm);
            float al = exp2f((m_i[ii] - mn) * LOG2E);
            m_i[ii] = mn;
            float ps = 0.f;
            #pragma unroll
            for (int jj = 0; jj < 4; jj++) {
                float p = exp2f((sacc[ii][jj] - mn) * LOG2E);
                sacc[ii][jj] = p;
                ps += p;
            }
            ps += __shfl_xor_sync(0xffffffffu, ps, 1);
            ps += __shfl_xor_sync(0xffffffffu, ps, 2);
            ps += __shfl_xor_sync(0xffffffffu, ps, 4);
            ps += __shfl_xor_sync(0xffffffffu, ps, 8);
            l_i[ii] = l_i[ii] * al + ps;
            #pragma unroll
            for (int jj = 0; jj < 4; jj++) o_acc[ii][jj] *= al;
        }

        __syncthreads();   // everyone done reading Ks before it becomes Ps
        #pragma unroll
        for (int jj = 0; jj < 4; jj++) {
            float4 p = make_float4(sacc[0][jj], sacc[1][jj], sacc[2][jj], sacc[3][jj]);
            *(float4*)&Ks[(tx * 4 + jj) * 68 + ty * 4] = p;   // Ps[kv][q]
        }
        __syncthreads();

        // O += P @ V
        #pragma unroll 16
        for (int kv = 0; kv < 64; kv++) {
            float4 p4 = *(const float4*)&Ks[kv * 68 + ty * 4];
            float4 v4 = *(const float4*)&Vs[kv * 68 + tx * 4];
            float pa[4] = {p4.x, p4.y, p4.z, p4.w};
            float va[4] = {v4.x, v4.y, v4.z, v4.w};
            #pragma unroll
            for (int ii = 0; ii < 4; ii++)
                #pragma unroll
                for (int jj = 0; jj < 4; jj++)
                    o_acc[ii][jj] = fmaf(pa[ii], va[jj], o_acc[ii][jj]);
        }
    }

    // write O in [B, S, H, D] (= row-major [8192, 1024]) for the O projection
    const int b = bh >> 4, h = bh & 15;
    #pragma unroll
    for (int ii = 0; ii < 4; ii++) {
        float inv = 1.0f / l_i[ii];
        int s = q0 + ty * 4 + ii;
        float4 o = make_float4(o_acc[ii][0] * inv, o_acc[ii][1] * inv,
                               o_acc[ii][2] * inv, o_acc[ii][3] * inv);
        *(float4*)(g_attn + (size_t)(b * 2048 + s) * 1024 + h * 64 + tx * 4) = o;
    }
}

// ---------------------------------------------------------------------------
// Output projection: out = g_attn @ Wo^T (plain GEMM, same tiling).
// ---------------------------------------------------------------------------
__global__ __launch_bounds__(256) void oproj_kernel(
    const float* __restrict__ Wo, float* __restrict__ out)
{
    __shared__ float As[32 * 132];
    __shared__ float Bs[32 * 68];

    const int tid = threadIdx.x;
    const int tx = tid & 15, ty = tid >> 4;
    const int m0 = blockIdx.y * 128;
    const int n0 = blockIdx.x * 64;
    const float* __restrict__ A = g_attn;

    float acc[8][4];
    #pragma unroll
    for (int i = 0; i < 8; i++)
        #pragma unroll
        for (int j = 0; j < 4; j++) acc[i][j] = 0.f;

    for (int k0 = 0; k0 < 1024; k0 += 32) {
        #pragma unroll
        for (int i = 0; i < 4; i++) {
            int idx = tid + i * 256;
            int row = idx >> 3, c4 = idx & 7;
            float4 v = *(const float4*)(A + (size_t)(m0 + row) * 1024 + k0 + c4 * 4);
            int o = (c4 * 4) * 132 + row;
            As[o] = v.x; As[o + 132] = v.y; As[o + 264] = v.z; As[o + 396] = v.w;
        }
        #pragma unroll
        for (int i = 0; i < 2; i++) {
            int idx = tid + i * 256;
            int row = idx >> 3, c4 = idx & 7;
            float4 v = *(const float4*)(Wo + (size_t)(n0 + row) * 1024 + k0 + c4 * 4);
            int o = (c4 * 4) * 68 + row;
            Bs[o] = v.x; Bs[o + 68] = v.y; Bs[o + 136] = v.z; Bs[o + 204] = v.w;
        }
        __syncthreads();
        #pragma unroll 16
        for (int k = 0; k < 32; k++) {
            float4 b4 = *(const float4*)&Bs[k * 68 + tx * 4];
            float4 a0 = *(const float4*)&As[k * 132 + ty * 8];
            float4 a1 = *(const float4*)&As[k * 132 + ty * 8 + 4];
            float a[8] = {a0.x, a0.y, a0.z, a0.w, a1.x, a1.y, a1.z, a1.w};
            float b[4] = {b4.x, b4.y, b4.z, b4.w};
            #pragma unroll
            for (int ii = 0; ii < 8; ii++)
                #pragma unroll
                for (int jj = 0; jj < 4; jj++)
                    acc[ii][jj] = fmaf(a[ii], b[jj], acc[ii][jj]);
        }
        __syncthreads();
    }

    #pragma unroll
    for (int ii = 0; ii < 8; ii++) {
        int m = m0 + ty * 8 + ii;
        float4 r = make_float4(acc[ii][0], acc[ii][1], acc[ii][2], acc[ii][3]);
        *(float4*)(out + (size_t)m * 1024 + n0 + tx * 4) = r;
    }
}

// ---------------------------------------------------------------------------
extern "C" void kernel_launch(void* const* d_in, const int* in_sizes, int n_in,
                              void* d_out, int out_size) {
    const float* x     = (const float*)d_in[0];
    const float* cos_f = (const float*)d_in[1];
    const float* sin_f = (const float*)d_in[2];
    // d_in[3] = causal_mask: unused (mask synthesized analytically)
    const float* wq    = (const float*)d_in[4];
    const float* wk    = (const float*)d_in[5];
    const float* wv    = (const float*)d_in[6];
    const float* wo    = (const float*)d_in[7];
    float* out = (float*)d_out;

    qkv_proj_kernel<<<dim3(48, 64), 256>>>(x, wq, wk, wv, cos_f, sin_f);

    cudaFuncSetAttribute(attn_kernel,
                         cudaFuncAttributeMaxDynamicSharedMemorySize, 52224);
    attn_kernel<<<dim3(32, 64), 256, 52224>>>();

    oproj_kernel<<<dim3(16, 64), 256>>>(wo, out);
}

// round 4
// speedup vs baseline: 7.4403x; 7.4403x over previous
#include <cuda_runtime.h>
#include <cuda_fp16.h>
#include <cstdint>

#define LOG2E 1.44269504088896f
#define SWZ(o) ((o) ^ (((o) >> 3) & 0x70))

// fp16 staging / intermediate buffers
__device__ __align__(16) __half g_xh[8388608];    // X as half [8192][1024]
__device__ __align__(16) __half g_whq[1048576];
__device__ __align__(16) __half g_whk[1048576];
__device__ __align__(16) __half g_whv[1048576];
__device__ __align__(16) __half g_who[1048576];
__device__ __align__(16) __half g_qh[8388608];    // [B*H][2048][64]
__device__ __align__(16) __half g_kh[8388608];
__device__ __align__(16) __half g_vh[8388608];
__device__ __align__(16) __half g_oh[8388608];    // attn out [8192][1024]

// ---------------------------------------------------------------------------
// helpers
// ---------------------------------------------------------------------------
__device__ __forceinline__ uint32_t smem_u32(const void* p) {
    uint32_t a;
    asm("{ .reg .u64 t; cvta.to.shared.u64 t, %1; cvt.u32.u64 %0, t; }"
        : "=r"(a) : "l"(p));
    return a;
}
__device__ __forceinline__ void cpa16(uint32_t s, const void* g) {
    asm volatile("cp.async.cg.shared.global [%0], [%1], 16;"
                 :: "r"(s), "l"(g) : "memory");
}
__device__ __forceinline__ void cp_commit() {
    asm volatile("cp.async.commit_group;" ::: "memory");
}
template <int N>
__device__ __forceinline__ void cp_wait() {
    asm volatile("cp.async.wait_group %0;" :: "n"(N) : "memory");
}
__device__ __forceinline__ void ldm_x4(uint32_t* r, uint32_t addr) {
    asm volatile("ldmatrix.sync.aligned.m8n8.x4.shared.b16 {%0,%1,%2,%3}, [%4];"
                 : "=r"(r[0]), "=r"(r[1]), "=r"(r[2]), "=r"(r[3]) : "r"(addr));
}
__device__ __forceinline__ void ldm_x4t(uint32_t* r, uint32_t addr) {
    asm volatile("ldmatrix.sync.aligned.m8n8.x4.trans.shared.b16 {%0,%1,%2,%3}, [%4];"
                 : "=r"(r[0]), "=r"(r[1]), "=r"(r[2]), "=r"(r[3]) : "r"(addr));
}
// D(f32) += A(f16 m16k16) * B(f16 col-major k16n8)
__device__ __forceinline__ void mma_f16(float* c, const uint32_t* a, const uint32_t* b) {
    asm volatile(
        "mma.sync.aligned.m16n8k16.row.col.f32.f16.f16.f32 "
        "{%0,%1,%2,%3}, {%4,%5,%6,%7}, {%8,%9}, {%0,%1,%2,%3};"
        : "+f"(c[0]), "+f"(c[1]), "+f"(c[2]), "+f"(c[3])
        : "r"(a[0]), "r"(a[1]), "r"(a[2]), "r"(a[3]), "r"(b[0]), "r"(b[1]));
}
__device__ __forceinline__ uint32_t packh2(float a, float b) {
    __half2 h = __floats2half2_rn(a, b);
    return *reinterpret_cast<uint32_t*>(&h);
}

// ---------------------------------------------------------------------------
// f32 -> f16 pre-pass for X and the 4 weight matrices (one launch)
// ---------------------------------------------------------------------------
__global__ __launch_bounds__(256) void f2h_multi(
    const float* __restrict__ x,  const float* __restrict__ wq,
    const float* __restrict__ wk, const float* __restrict__ wv,
    const float* __restrict__ wo)
{
    int i = blockIdx.x * 256 + threadIdx.x;   // float4 index, total 3145728
    const float4* s;
    __half* d;
    int off;
    if (i < 2097152) { s = (const float4*)x; d = g_xh; off = i; }
    else {
        int r = i - 2097152;
        int w = r >> 18;
        off = r & 262143;
        s = (const float4*)(w == 0 ? wq : w == 1 ? wk : w == 2 ? wv : wo);
        d = (w == 0) ? g_whq : (w == 1) ? g_whk : (w == 2) ? g_whv : g_who;
    }
    float4 v = s[off];
    uint2 u;
    u.x = packh2(v.x, v.y);
    u.y = packh2(v.z, v.w);
    *reinterpret_cast<uint2*>(d + (size_t)off * 4) = u;
}

// ---------------------------------------------------------------------------
// f16 MMA GEMM mainloop: C[128,128] = A[128rows,1024] * B[128rows,1024]^T.
// BK=64 halves (128B rows, SW128-style XOR swizzle), 3-stage cp.async.
// 8 warps = 4(m) x 2(n); warp tile 32x64.  acc[mf][nf][reg] f32.
// ---------------------------------------------------------------------------
__device__ __forceinline__ void gemm_mainloop_f16(
    const __half* __restrict__ A, const __half* __restrict__ B,
    int m0, int n0, uint32_t sbase, float (&acc)[2][8][4])
{
    const int tid = threadIdx.x, lane = tid & 31, warp = tid >> 5;
    const int lr = lane & 7, lmat = lane >> 3;
    const int wm = (warp & 3) * 32, wn = (warp >> 2) * 64;
    const int srow = tid >> 3, sch = tid & 7;

    const __half* ga[4];
    const __half* gb[4];
    uint32_t swo[4];
    #pragma unroll
    for (int j = 0; j < 4; j++) {
        int row = srow + j * 32;
        ga[j] = A + (size_t)(m0 + row) * 1024 + sch * 8;
        gb[j] = B + (size_t)(n0 + row) * 1024 + sch * 8;
        swo[j] = SWZ((uint32_t)(row * 128 + sch * 16));
    }
    #pragma unroll
    for (int a = 0; a < 2; a++)
        #pragma unroll
        for (int b = 0; b < 8; b++)
            #pragma unroll
            for (int r = 0; r < 4; r++) acc[a][b][r] = 0.f;

    auto ISSUE = [&](int s) {
        uint32_t ab = sbase + (s % 3) * 32768, bb = ab + 16384;
        #pragma unroll
        for (int j = 0; j < 4; j++) {
            cpa16(ab + swo[j], ga[j] + s * 64);
            cpa16(bb + swo[j], gb[j] + s * 64);
        }
        cp_commit();
    };

    ISSUE(0); ISSUE(1);
    for (int i = 0; i < 16; i++) {
        if (i + 2 < 16)      { ISSUE(i + 2); cp_wait<2>(); }
        else if (i + 1 < 16) { cp_wait<1>(); }
        else                 { cp_wait<0>(); }
        __syncthreads();
        uint32_t ab = sbase + (i % 3) * 32768, bb = ab + 16384;
        #pragma unroll
        for (int kk = 0; kk < 4; kk++) {
            const int c0 = kk * 2;
            uint32_t a[2][4];
            #pragma unroll
            for (int mf = 0; mf < 2; mf++) {
                int row = wm + mf * 16 + lr + (lmat & 1) * 8;
                int ch  = c0 + (lmat >> 1);
                ldm_x4(a[mf], ab + SWZ((uint32_t)(row * 128 + ch * 16)));
            }
            #pragma unroll
            for (int q = 0; q < 4; q++) {
                uint32_t bq[4];
                int row = wn + q * 16 + lr + (lmat >> 1) * 8;
                int ch  = c0 + (lmat & 1);
                ldm_x4(bq, bb + SWZ((uint32_t)(row * 128 + ch * 16)));
                #pragma unroll
                for (int mf = 0; mf < 2; mf++) {
                    mma_f16(acc[mf][2 * q],     a[mf], bq);
                    mma_f16(acc[mf][2 * q + 1], a[mf], bq + 2);
                }
            }
        }
        __syncthreads();
    }
}

// ---------------------------------------------------------------------------
// QKV projection (+RoPE).  grid (24, 64): x -> wsel*8 + ntile, y -> m tile.
// ---------------------------------------------------------------------------
__global__ __launch_bounds__(256) void qkv_mma_kernel(
    const float* __restrict__ cos_f, const float* __restrict__ sin_f)
{
    extern __shared__ char dyn[];
    uint32_t sbase = (smem_u32(dyn) + 1023u) & ~1023u;
    const int tid = threadIdx.x, lane = tid & 31, warp = tid >> 5;
    const int wm = (warp & 3) * 32, wn = (warp >> 2) * 64;
    const int wsel = blockIdx.x >> 3;
    const int n0 = (blockIdx.x & 7) * 128;
    const int m0 = blockIdx.y * 128;
    const __half* B = (wsel == 0) ? g_whq : (wsel == 1) ? g_whk : g_whv;

    float acc[2][8][4];
    gemm_mainloop_f16(g_xh, B, m0, n0, sbase, acc);

    __half* dst = (wsel == 0) ? g_qh : (wsel == 1) ? g_kh : g_vh;
    const int r0 = lane >> 2, cc = (lane & 3) * 2;
    #pragma unroll
    for (int mf = 0; mf < 2; mf++) {
        int m = m0 + wm + mf * 16 + r0;
        int s0 = m & 2047, bidx = m >> 11;
        #pragma unroll
        for (int nf = 0; nf < 8; nf++) {
            int n = n0 + wn + nf * 8 + cc;
            int h = n >> 6, d = n & 63;
            size_t a0 = ((size_t)(bidx * 16 + h) * 2048 + s0) * 64 + d;
            size_t a1 = a0 + 8 * 64;
            if (wsel < 2) {
                int fi = d >> 1;
                float c0v = cos_f[s0 * 32 + fi],       s0v = sin_f[s0 * 32 + fi];
                float c1v = cos_f[(s0 + 8) * 32 + fi], s1v = sin_f[(s0 + 8) * 32 + fi];
                float e0 = acc[mf][nf][0], o0 = acc[mf][nf][1];
                float e1 = acc[mf][nf][2], o1 = acc[mf][nf][3];
                *reinterpret_cast<uint32_t*>(&dst[a0]) =
                    packh2(e0 * c0v - o0 * s0v, e0 * s0v + o0 * c0v);
                *reinterpret_cast<uint32_t*>(&dst[a1]) =
                    packh2(e1 * c1v - o1 * s1v, e1 * s1v + o1 * c1v);
            } else {
                *reinterpret_cast<uint32_t*>(&dst[a0]) =
                    packh2(acc[mf][nf][0], acc[mf][nf][1]);
                *reinterpret_cast<uint32_t*>(&dst[a1]) =
                    packh2(acc[mf][nf][2], acc[mf][nf][3]);
            }
        }
    }
}

// ---------------------------------------------------------------------------
// Output projection: out(f32) = g_oh @ Wo^T.  grid (8, 64).
// ---------------------------------------------------------------------------
__global__ __launch_bounds__(256) void oproj_mma_kernel(float* __restrict__ out)
{
    extern __shared__ char dyn[];
    uint32_t sbase = (smem_u32(dyn) + 1023u) & ~1023u;
    const int tid = threadIdx.x, lane = tid & 31, warp = tid >> 5;
    const int wm = (warp & 3) * 32, wn = (warp >> 2) * 64;
    const int n0 = blockIdx.x * 128;
    const int m0 = blockIdx.y * 128;

    float acc[2][8][4];
    gemm_mainloop_f16(g_oh, g_who, m0, n0, sbase, acc);

    const int r0 = lane >> 2, cc = (lane & 3) * 2;
    #pragma unroll
    for (int mf = 0; mf < 2; mf++) {
        int m = m0 + wm + mf * 16 + r0;
        #pragma unroll
        for (int nf = 0; nf < 8; nf++) {
            int n = n0 + wn + nf * 8 + cc;
            *reinterpret_cast<float2*>(&out[(size_t)m * 1024 + n]) =
                make_float2(acc[mf][nf][0], acc[mf][nf][1]);
            *reinterpret_cast<float2*>(&out[(size_t)(m + 8) * 1024 + n]) =
                make_float2(acc[mf][nf][2], acc[mf][nf][3]);
        }
    }
}

// ---------------------------------------------------------------------------
// Flash attention on mma.sync.  Block: 128q x 64kv, 8 warps (each 16q x 64kv).
// grid (16 q-tiles, 64 bh).  cp.async double-buffered K/V, Q loaded once.
// ---------------------------------------------------------------------------
__global__ __launch_bounds__(256) void attn_mma_kernel()
{
    extern __shared__ char dyn[];
    uint32_t sbase = (smem_u32(dyn) + 1023u) & ~1023u;
    const uint32_t Qs = sbase, Ks0 = sbase + 16384, Vs0 = sbase + 32768;

    const int tid = threadIdx.x, lane = tid & 31, warp = tid >> 5;
    const int lr = lane & 7, lmat = lane >> 3;
    const int T = blockIdx.x, bh = blockIdx.y;
    const int q0 = T * 128;
    const __half* Qg = g_qh + (size_t)bh * 2048 * 64;
    const __half* Kg = g_kh + (size_t)bh * 2048 * 64;
    const __half* Vg = g_vh + (size_t)bh * 2048 * 64;

    // Q staging: 1024 chunks of 16B
    const int qrow = tid >> 1, qcb = (tid & 1) * 4;
    #pragma unroll
    for (int j = 0; j < 4; j++)
        cpa16(Qs + SWZ((uint32_t)(qrow * 128 + (qcb + j) * 16)),
              Qg + (size_t)(q0 + qrow) * 64 + (qcb + j) * 8);

    const int krow = tid >> 2, kcb = (tid & 3) * 2;
    auto ISSUEKV = [&](int t) {
        uint32_t kb = Ks0 + (t & 1) * 8192, vb = Vs0 + (t & 1) * 8192;
        #pragma unroll
        for (int j = 0; j < 2; j++) {
            uint32_t so = SWZ((uint32_t)(krow * 128 + (kcb + j) * 16));
            const size_t go = (size_t)(t * 64 + krow) * 64 + (kcb + j) * 8;
            cpa16(kb + so, Kg + go);
            cpa16(vb + so, Vg + go);
        }
        cp_commit();
    };
    ISSUEKV(0);   // commit covers Q chunks too

    const int nt = 2 * T + 2;
    const int r0 = lane >> 2, cc = (lane & 3) * 2;
    const int qg0 = q0 + warp * 16 + r0;
    float m0r = -1e30f, m1r = -1e30f, l0 = 0.f, l1 = 0.f;
    float oacc[8][4];
    #pragma unroll
    for (int f = 0; f < 8; f++)
        #pragma unroll
        for (int r = 0; r < 4; r++) oacc[f][r] = 0.f;

    for (int t = 0; t < nt; t++) {
        if (t + 1 < nt) { ISSUEKV(t + 1); cp_wait<1>(); }
        else            { cp_wait<0>(); }
        __syncthreads();
        const uint32_t kb = Ks0 + (t & 1) * 8192, vb = Vs0 + (t & 1) * 8192;

        // S = Q K^T
        float sacc[8][4];
        #pragma unroll
        for (int f = 0; f < 8; f++)
            #pragma unroll
            for (int r = 0; r < 4; r++) sacc[f][r] = 0.f;
        #pragma unroll
        for (int kk = 0; kk < 4; kk++) {
            const int c0 = kk * 2;
            uint32_t qa[4];
            {
                int row = warp * 16 + lr + (lmat & 1) * 8;
                int ch  = c0 + (lmat >> 1);
                ldm_x4(qa, Qs + SWZ((uint32_t)(row * 128 + ch * 16)));
            }
            #pragma unroll
            for (int q = 0; q < 4; q++) {
                uint32_t kf[4];
                int row = q * 16 + lr + (lmat >> 1) * 8;
                int ch  = c0 + (lmat & 1);
                ldm_x4(kf, kb + SWZ((uint32_t)(row * 128 + ch * 16)));
                mma_f16(sacc[2 * q],     qa, kf);
                mma_f16(sacc[2 * q + 1], qa, kf + 2);
            }
        }

        // scale + causal mask + online softmax
        const int kv0 = t * 64;
        const bool domask = (kv0 + 63 > q0 + warp * 16);
        float mx0 = -1e30f, mx1 = -1e30f;
        #pragma unroll
        for (int f = 0; f < 8; f++) {
            int kvb = kv0 + f * 8 + cc;
            #pragma unroll
            for (int j = 0; j < 4; j++) {
                float v = sacc[f][j] * 0.125f;
                if (domask) {
                    int kvj = kvb + (j & 1);
                    int qi  = (j < 2) ? qg0 : (qg0 + 8);
                    if (kvj > qi) v = -1e30f;
                }
                sacc[f][j] = v;
                if (j < 2) mx0 = fmaxf(mx0, v); else mx1 = fmaxf(mx1, v);
            }
        }
        mx0 = fmaxf(mx0, __shfl_xor_sync(0xffffffffu, mx0, 1));
        mx0 = fmaxf(mx0, __shfl_xor_sync(0xffffffffu, mx0, 2));
        mx1 = fmaxf(mx1, __shfl_xor_sync(0xffffffffu, mx1, 1));
        mx1 = fmaxf(mx1, __shfl_xor_sync(0xffffffffu, mx1, 2));
        float mn0 = fmaxf(m0r, mx0), mn1 = fmaxf(m1r, mx1);
        float al0 = exp2f((m0r - mn0) * LOG2E), al1 = exp2f((m1r - mn1) * LOG2E);
        m0r = mn0; m1r = mn1;
        float s0 = 0.f, s1 = 0.f;
        #pragma unroll
        for (int f = 0; f < 8; f++) {
            #pragma unroll
            for (int j = 0; j < 4; j++) {
                float p = exp2f((sacc[f][j] - ((j < 2) ? mn0 : mn1)) * LOG2E);
                sacc[f][j] = p;
                if (j < 2) s0 += p; else s1 += p;
            }
        }
        s0 += __shfl_xor_sync(0xffffffffu, s0, 1);
        s0 += __shfl_xor_sync(0xffffffffu, s0, 2);
        s1 += __shfl_xor_sync(0xffffffffu, s1, 1);
        s1 += __shfl_xor_sync(0xffffffffu, s1, 2);
        l0 = l0 * al0 + s0;
        l1 = l1 * al1 + s1;
        #pragma unroll
        for (int f = 0; f < 8; f++) {
            oacc[f][0] *= al0; oacc[f][1] *= al0;
            oacc[f][2] *= al1; oacc[f][3] *= al1;
        }

        // P (C-frags) -> A-frags, in registers
        uint32_t pa[4][4];
        #pragma unroll
        for (int kk = 0; kk < 4; kk++) {
            pa[kk][0] = packh2(sacc[2 * kk][0],     sacc[2 * kk][1]);
            pa[kk][1] = packh2(sacc[2 * kk][2],     sacc[2 * kk][3]);
            pa[kk][2] = packh2(sacc[2 * kk + 1][0], sacc[2 * kk + 1][1]);
            pa[kk][3] = packh2(sacc[2 * kk + 1][2], sacc[2 * kk + 1][3]);
        }

        // O += P @ V  (V row-major, B-frags via ldmatrix.trans)
        #pragma unroll
        for (int kk = 0; kk < 4; kk++) {
            #pragma unroll
            for (int q = 0; q < 4; q++) {
                uint32_t vf[4];
                int row = kk * 16 + lr + (lmat & 1) * 8;
                int ch  = q * 2 + (lmat >> 1);
                ldm_x4t(vf, vb + SWZ((uint32_t)(row * 128 + ch * 16)));
                mma_f16(oacc[2 * q],     pa[kk], vf);
                mma_f16(oacc[2 * q + 1], pa[kk], vf + 2);
            }
        }
        __syncthreads();
    }

    // epilogue -> g_oh half [B][S][1024]
    float inv0 = 1.f / l0, inv1 = 1.f / l1;
    const int b = bh >> 4, hh = bh & 15;
    #pragma unroll
    for (int f = 0; f < 8; f++) {
        int d = hh * 64 + f * 8 + cc;
        size_t a0 = ((size_t)b * 2048 + qg0) * 1024 + d;
        *reinterpret_cast<uint32_t*>(&g_oh[a0]) =
            packh2(oacc[f][0] * inv0, oacc[f][1] * inv0);
        *reinterpret_cast<uint32_t*>(&g_oh[a0 + 8 * 1024]) =
            packh2(oacc[f][2] * inv1, oacc[f][3] * inv1);
    }
}

// ---------------------------------------------------------------------------
extern "C" void kernel_launch(void* const* d_in, const int* in_sizes, int n_in,
                              void* d_out, int out_size) {
    const float* x     = (const float*)d_in[0];
    const float* cos_f = (const float*)d_in[1];
    const float* sin_f = (const float*)d_in[2];
    // d_in[3] = causal_mask: unused (mask synthesized analytically)
    const float* wq    = (const float*)d_in[4];
    const float* wk    = (const float*)d_in[5];
    const float* wv    = (const float*)d_in[6];
    const float* wo    = (const float*)d_in[7];
    float* out = (float*)d_out;

    const int GEMM_SMEM = 99328;   // 3 stages x 32KB + align slack
    const int ATTN_SMEM = 50176;   // Q 16KB + 2x(K 8KB + V 8KB) + slack
    cudaFuncSetAttribute(qkv_mma_kernel,
                         cudaFuncAttributeMaxDynamicSharedMemorySize, GEMM_SMEM);
    cudaFuncSetAttribute(oproj_mma_kernel,
                         cudaFuncAttributeMaxDynamicSharedMemorySize, GEMM_SMEM);
    cudaFuncSetAttribute(attn_mma_kernel,
                         cudaFuncAttributeMaxDynamicSharedMemorySize, ATTN_SMEM);

    f2h_multi<<<12288, 256>>>(x, wq, wk, wv, wo);
    qkv_mma_kernel<<<dim3(24, 64), 256, GEMM_SMEM>>>(cos_f, sin_f);
    attn_mma_kernel<<<dim3(16, 64), 256, ATTN_SMEM>>>();
    oproj_mma_kernel<<<dim3(8, 64), 256, GEMM_SMEM>>>(out);
}